// round 17
// baseline (speedup 1.0000x reference)
#include <cuda_runtime.h>
#include <cuda_bf16.h>
#include <cuda_fp16.h>
#include <cuda_fp8.h>
#include <math.h>
#include <stdint.h>

#define T_ 512
#define D_ 2048
#define I_ 768
#define E_ 16
#define K_ 8

// ---------------- helpers ----------------
__device__ __forceinline__ uint32_t smem_u32(const void* p) {
    uint32_t a;
    asm("{ .reg .u64 t; cvta.to.shared.u64 t, %1; cvt.u32.u64 %0, t; }" : "=r"(a) : "l"(p));
    return a;
}
__device__ __forceinline__ void ldm_x4(uint32_t* r, uint32_t addr) {
    asm volatile("ldmatrix.sync.aligned.m8n8.x4.shared.b16 {%0,%1,%2,%3}, [%4];"
        : "=r"(r[0]), "=r"(r[1]), "=r"(r[2]), "=r"(r[3]) : "r"(addr));
}
__device__ __forceinline__ void mma_bf16(float* c, const uint32_t* a, const uint32_t* b) {
    asm volatile("mma.sync.aligned.m16n8k16.row.col.f32.bf16.bf16.f32 "
        "{%0,%1,%2,%3}, {%4,%5,%6,%7}, {%8,%9}, {%0,%1,%2,%3};"
        : "+f"(c[0]), "+f"(c[1]), "+f"(c[2]), "+f"(c[3])
        : "r"(a[0]), "r"(a[1]), "r"(a[2]), "r"(a[3]), "r"(b[0]), "r"(b[1]));
}
__device__ __forceinline__ void mma_f16(float* c, const uint32_t* a, const uint32_t* b) {
    asm volatile("mma.sync.aligned.m16n8k16.row.col.f32.f16.f16.f32 "
        "{%0,%1,%2,%3}, {%4,%5,%6,%7}, {%8,%9}, {%0,%1,%2,%3};"
        : "+f"(c[0]), "+f"(c[1]), "+f"(c[2]), "+f"(c[3])
        : "r"(a[0]), "r"(a[1]), "r"(a[2]), "r"(a[3]), "r"(b[0]), "r"(b[1]));
}
#define CP16(smem_addr, gptr) \
    asm volatile("cp.async.cg.shared.global [%0], [%1], 16;" :: "r"(smem_addr), "l"(gptr) : "memory")
#define CP_COMMIT() asm volatile("cp.async.commit_group;" ::: "memory")
#define CP_WAIT0()  asm volatile("cp.async.wait_group 0;" ::: "memory")

// ---------------- scratch ----------------
__device__ __nv_bfloat16 g_xb[T_ * D_];   // quant-dequantized activations (exact bf16)
__device__ __half g_ah[E_ * T_ * I_];     // activation a/64 in fp16
__device__ int   g_tok[E_ * T_];
__device__ int   g_cnt[E_];
__device__ float g_comb[T_ * E_];
__device__ int   g_flag[T_ * E_];

__constant__ float c_fp4[16] = {0.0f, 0.5f, 1.0f, 1.5f, 2.0f, 3.0f, 4.0f, 6.0f,
                                -0.0f, -0.5f, -1.0f, -1.5f, -2.0f, -3.0f, -4.0f, -6.0f};

// ---------------- fused preamble ----------------
__global__ void prep_kernel(const float* __restrict__ x,
                            const float* __restrict__ tw,
                            const int* __restrict__ tids,
                            float* __restrict__ out) {
    const int i = blockIdx.x * blockDim.x + threadIdx.x;
    if (i < T_ * D_) out[i] = 0.0f;

    {
        int g = i >> 5, lane = i & 31;
        if (g < (T_ * D_) / 32) {
            float v = x[g * 32 + lane];
            float av = fabsf(v);
            #pragma unroll
            for (int o = 16; o; o >>= 1) av = fmaxf(av, __shfl_xor_sync(0xffffffffu, av, o));
            av = fmaxf(av, 1e-4f);
            float scale = av / 448.0f;
            unsigned bits = __float_as_uint(scale);
            unsigned exp = ((bits >> 23) & 255u) + ((bits & 0x7fffffu) ? 1u : 0u);
            exp = min(max(exp, 1u), 254u);
            float rscale = __uint_as_float(exp << 23);
            float inv = 1.0f / rscale;
            __nv_fp8_storage_t q = __nv_cvt_float_to_fp8(v * inv, __NV_SATFINITE, __NV_E4M3);
            float qf = __half2float(__half(__nv_cvt_fp8_to_halfraw(q, __NV_E4M3)));
            g_xb[g * 32 + lane] = __float2bfloat16(qf * rscale);
        }
    }

    if (i < T_) {
        int ids[K_]; float w[K_];
        #pragma unroll
        for (int k = 0; k < K_; k++) { ids[k] = tids[i * K_ + k]; w[k] = tw[i * K_ + k]; }
        #pragma unroll
        for (int e = 0; e < E_; e++) {
            float s = 0.0f; int f = 0;
            #pragma unroll
            for (int k = 0; k < K_; k++)
                if (ids[k] == e) { s += w[k]; f = 1; }
            g_comb[i * E_ + e] = s;
            g_flag[i * E_ + e] = f;
        }
    }
}

__global__ void route_compact_par() {
    __shared__ int s[T_];
    const int e = blockIdx.x;
    const int t = threadIdx.x;
    int f = g_flag[t * E_ + e];
    s[t] = f;
    __syncthreads();
    #pragma unroll
    for (int off = 1; off < T_; off <<= 1) {
        int v = (t >= off) ? s[t - off] : 0;
        __syncthreads();
        s[t] += v;
        __syncthreads();
    }
    if (f) g_tok[e * T_ + s[t] - 1] = t;
    if (t == T_ - 1) g_cnt[e] = s[t];
}

// fp4 byte -> packed bf16x2 / f16x2, scaled
__device__ __forceinline__ uint32_t dq2(int w, float s, const float* tab) {
    float lo = tab[w & 15] * s;
    float hi = tab[(w >> 4) & 15] * s;
    __nv_bfloat162 h = __floats2bfloat162_rn(lo, hi);
    return *reinterpret_cast<uint32_t*>(&h);
}
__device__ __forceinline__ uint32_t dq2h(int w, float s, const float* tab) {
    float lo = tab[w & 15] * s;
    float hi = tab[(w >> 4) & 15] * s;
    __half2 h = __floats2half2_rn(lo, hi);
    return *reinterpret_cast<uint32_t*>(&h);
}
__device__ __forceinline__ uint4 dq8(int4 w, float s, const float* tab) {
    uint4 o;
    o.x = dq2(w.x, s, tab); o.y = dq2(w.y, s, tab);
    o.z = dq2(w.z, s, tab); o.w = dq2(w.w, s, tab);
    return o;
}
__device__ __forceinline__ uint4 dq8h(int4 w, float s, const float* tab) {
    uint4 o;
    o.x = dq2h(w.x, s, tab); o.y = dq2h(w.y, s, tab);
    o.z = dq2h(w.z, s, tab); o.w = dq2h(w.w, s, tab);
    return o;
}

#define RSX 144                 // 64 elems x 2B + 16B pad (conflict-free ldmatrix)
#define STGX (256 * RSX)        // one stage: A rows 0-127, B rows 128-255 = 36864 B
#define DYN_SMEM (2 * STGX)

// ================= GEMM1: h = x @ w13^T, a = silu(g)*u =================
// 128 thr, block m128 x (G64+U64), warps 2m x 2n, warp m64 x (G32+U32), BK=64, cp.async A
__global__ void __launch_bounds__(128, 2)
gemm1_kernel(const int* __restrict__ w13, const int* __restrict__ w13s) {
    const int e = blockIdx.z;
    const int cnt = g_cnt[e];
    const int m0 = blockIdx.y * 128;
    if (m0 >= cnt) return;
    const int n0 = blockIdx.x * 64;

    extern __shared__ __align__(16) unsigned char dsm[];
    __shared__ float tab[16];
    __shared__ int toks[128];

    const int tid = threadIdx.x, wid = tid >> 5, lid = tid & 31;
    if (tid < 16) tab[tid] = c_fp4[tid];
    if (tid < 128) toks[tid] = g_tok[e * T_ + min(m0 + tid, cnt - 1)];
    __syncthreads();

    const int* we = w13 + (size_t)e * (2 * I_) * (D_ / 2);
    const int* se = w13s + (size_t)e * (2 * I_) * (D_ / 32);
    const uint32_t smB = smem_u32(dsm);
    const int wm = wid >> 1, wn = wid & 1;

    // A cp.async coords: 8 copies/thread; row = (tid>>3)+16i, seg = tid&7 (coalesced 128B rows)
    const int arow0 = tid >> 3, aseg = tid & 7;
    // B coords: 8 int4/thread; j = tid + 128i: brow = j>>3, bseg = j&7 (coalesced 128B rows)
    // feat: brow<64 -> gate n0+brow ; else up I_+n0+brow-64. smem row = 128+brow.
    const int brow0 = tid >> 3, bseg = tid & 7;

    float cg[4][4][4] = {};
    float cu[4][4][4] = {};

    int4 pw[8]; float ps[8];

    // ---- prologue ----
    // cp.async A(0) -> stage0
    #pragma unroll
    for (int i = 0; i < 8; i++) {
        int row = arow0 + 16 * i;
        CP16(smB + row * RSX + aseg * 16,
             (const char*)&g_xb[(size_t)toks[row] * D_ + aseg * 8]);
    }
    CP_COMMIT();
    // LDG B(0)
    #pragma unroll
    for (int i = 0; i < 8; i++) {
        int brow = brow0 + 16 * i;
        int f = (brow < 64) ? (n0 + brow) : (I_ + n0 + brow - 64);
        pw[i] = *(const int4*)&we[(size_t)f * (D_ / 2) + bseg * 4];
        ps[i] = __uint_as_float((unsigned)se[(size_t)f * (D_ / 32) + (bseg >> 2)] << 23);
    }
    // STS B(0) -> stage0
    #pragma unroll
    for (int i = 0; i < 8; i++) {
        int brow = brow0 + 16 * i;
        *(uint4*)(dsm + (128 + brow) * RSX + bseg * 16) = dq8(pw[i], ps[i], tab);
    }
    // LDG B(1)
    #pragma unroll
    for (int i = 0; i < 8; i++) {
        int brow = brow0 + 16 * i;
        int f = (brow < 64) ? (n0 + brow) : (I_ + n0 + brow - 64);
        pw[i] = *(const int4*)&we[(size_t)f * (D_ / 2) + 32 + bseg * 4];
        ps[i] = __uint_as_float((unsigned)se[(size_t)f * (D_ / 32) + 2 + (bseg >> 2)] << 23);
    }
    CP_WAIT0();
    __syncthreads();

    const int NC = D_ / 64;
    for (int c = 0; c < NC; c++) {
        const uint32_t sb = smB + (c & 1) * STGX;
        unsigned char* so = dsm + ((c + 1) & 1) * STGX;
        // issue cp.async A(c+1) -> other stage (its readers done before last barrier)
        if (c + 1 < NC) {
            const int k0 = (c + 1) * 64;
            #pragma unroll
            for (int i = 0; i < 8; i++) {
                int row = arow0 + 16 * i;
                CP16(smem_u32(so) + row * RSX + aseg * 16,
                     (const char*)&g_xb[(size_t)toks[row] * D_ + k0 + aseg * 8]);
            }
            CP_COMMIT();
        }
        // MMA on stage c&1
        #pragma unroll
        for (int kk = 0; kk < 4; kk++) {
            uint32_t af[4][4];
            #pragma unroll
            for (int mf = 0; mf < 4; mf++)
                ldm_x4(af[mf], sb + (wm * 64 + mf * 16 + (lid & 15)) * RSX + kk * 32 + (lid >> 4) * 16);
            const int nrow_off = ((lid >> 4) << 3) + (lid & 7);
            const int bcol = kk * 32 + ((lid >> 3) & 1) * 16;
            uint32_t bg[2][4], bu[2][4];
            #pragma unroll
            for (int ng = 0; ng < 2; ng++) {
                int nr = wn * 32 + ng * 16 + nrow_off;
                ldm_x4(bg[ng], sb + (128 + nr) * RSX + bcol);
                ldm_x4(bu[ng], sb + (192 + nr) * RSX + bcol);
            }
            #pragma unroll
            for (int mf = 0; mf < 4; mf++)
                #pragma unroll
                for (int ng = 0; ng < 2; ng++)
                    #pragma unroll
                    for (int sub = 0; sub < 2; sub++) {
                        mma_bf16(cg[mf][ng * 2 + sub], af[mf], &bg[ng][sub * 2]);
                        mma_bf16(cu[mf][ng * 2 + sub], af[mf], &bu[ng][sub * 2]);
                    }
        }
        // STS B(c+1)
        if (c + 1 < NC) {
            #pragma unroll
            for (int i = 0; i < 8; i++) {
                int brow = brow0 + 16 * i;
                *(uint4*)(so + (128 + brow) * RSX + bseg * 16) = dq8(pw[i], ps[i], tab);
            }
        }
        CP_WAIT0();
        __syncthreads();
        // LDG B(c+2)
        if (c + 2 < NC) {
            const int k0 = (c + 2) * 64;
            #pragma unroll
            for (int i = 0; i < 8; i++) {
                int brow = brow0 + 16 * i;
                int f = (brow < 64) ? (n0 + brow) : (I_ + n0 + brow - 64);
                pw[i] = *(const int4*)&we[(size_t)f * (D_ / 2) + (k0 >> 1) + bseg * 4];
                ps[i] = __uint_as_float((unsigned)se[(size_t)f * (D_ / 32) + (k0 >> 5) + (bseg >> 2)] << 23);
            }
        }
    }

    // epilogue: a = silu(g)*u, store a/64 as fp16
    #pragma unroll
    for (int mf = 0; mf < 4; mf++) {
        const int rbase = wm * 64 + mf * 16 + (lid >> 2);
        #pragma unroll
        for (int half = 0; half < 2; half++) {
            int m = m0 + rbase + half * 8;
            if (m < cnt) {
                size_t rowp = ((size_t)e * T_ + m) * I_ + n0;
                #pragma unroll
                for (int nf = 0; nf < 4; nf++) {
                    float g0 = cg[mf][nf][half * 2 + 0], g1 = cg[mf][nf][half * 2 + 1];
                    float u0 = cu[mf][nf][half * 2 + 0], u1 = cu[mf][nf][half * 2 + 1];
                    float a0 = g0 * u0 / (1.0f + __expf(-g0)) * 0.015625f;
                    float a1 = g1 * u1 / (1.0f + __expf(-g1)) * 0.015625f;
                    int col = wn * 32 + nf * 8 + (lid & 3) * 2;
                    __half2 h2 = __floats2half2_rn(a0, a1);
                    *(uint32_t*)&g_ah[rowp + col] = *(uint32_t*)&h2;
                }
            }
        }
    }
}

// ================= GEMM2: out += (64*comb) * ((a/64) @ w2^T) =================
// 128 thr, block m128 x n128, warps 2m x 2n, warp 64 x 64, BK=64, cp.async A
__global__ void __launch_bounds__(128, 2)
gemm2_kernel(const int* __restrict__ w2, const int* __restrict__ w2s, float* __restrict__ out) {
    const int e = blockIdx.z;
    const int cnt = g_cnt[e];
    const int m0 = blockIdx.y * 128;
    if (m0 >= cnt) return;
    const int n0 = blockIdx.x * 128;

    extern __shared__ __align__(16) unsigned char dsm[];
    __shared__ float tab[16];
    __shared__ int toks[128];

    const int tid = threadIdx.x, wid = tid >> 5, lid = tid & 31;
    if (tid < 16) tab[tid] = c_fp4[tid];
    if (tid < 128) toks[tid] = g_tok[e * T_ + min(m0 + tid, cnt - 1)];
    __syncthreads();

    const int* we = w2 + (size_t)e * D_ * (I_ / 2);
    const int* se = w2s + (size_t)e * D_ * (I_ / 32);
    const uint32_t smB = smem_u32(dsm);
    const int wm = wid >> 1, wn = wid & 1;

    const int arow0 = tid >> 3, aseg = tid & 7;
    const int brow0 = tid >> 3, bseg = tid & 7;

    float acc[4][8][4] = {};

    int4 pw[8]; float ps[8];

    // ---- prologue ----
    #pragma unroll
    for (int i = 0; i < 8; i++) {
        int row = arow0 + 16 * i;
        CP16(smB + row * RSX + aseg * 16,
             (const char*)&g_ah[((size_t)e * T_ + m0 + row) * I_ + aseg * 8]);
    }
    CP_COMMIT();
    #pragma unroll
    for (int i = 0; i < 8; i++) {
        int f = n0 + brow0 + 16 * i;
        pw[i] = *(const int4*)&we[(size_t)f * (I_ / 2) + bseg * 4];
        ps[i] = __uint_as_float((unsigned)se[(size_t)f * (I_ / 32) + (bseg >> 2)] << 23);
    }
    #pragma unroll
    for (int i = 0; i < 8; i++) {
        int brow = brow0 + 16 * i;
        *(uint4*)(dsm + (128 + brow) * RSX + bseg * 16) = dq8h(pw[i], ps[i], tab);
    }
    #pragma unroll
    for (int i = 0; i < 8; i++) {
        int f = n0 + brow0 + 16 * i;
        pw[i] = *(const int4*)&we[(size_t)f * (I_ / 2) + 32 + bseg * 4];
        ps[i] = __uint_as_float((unsigned)se[(size_t)f * (I_ / 32) + 2 + (bseg >> 2)] << 23);
    }
    CP_WAIT0();
    __syncthreads();

    const int NC = I_ / 64;
    for (int c = 0; c < NC; c++) {
        const uint32_t sb = smB + (c & 1) * STGX;
        unsigned char* so = dsm + ((c + 1) & 1) * STGX;
        if (c + 1 < NC) {
            const int k0 = (c + 1) * 64;
            #pragma unroll
            for (int i = 0; i < 8; i++) {
                int row = arow0 + 16 * i;
                CP16(smem_u32(so) + row * RSX + aseg * 16,
                     (const char*)&g_ah[((size_t)e * T_ + m0 + row) * I_ + k0 + aseg * 8]);
            }
            CP_COMMIT();
        }
        #pragma unroll
        for (int kk = 0; kk < 4; kk++) {
            uint32_t af[4][4];
            #pragma unroll
            for (int mf = 0; mf < 4; mf++)
                ldm_x4(af[mf], sb + (wm * 64 + mf * 16 + (lid & 15)) * RSX + kk * 32 + (lid >> 4) * 16);
            const int nrow_off = ((lid >> 4) << 3) + (lid & 7);
            const int bcol = kk * 32 + ((lid >> 3) & 1) * 16;
            #pragma unroll
            for (int hn = 0; hn < 2; hn++) {
                uint32_t bb[2][4];
                #pragma unroll
                for (int ng = 0; ng < 2; ng++) {
                    int nr = wn * 64 + (hn * 2 + ng) * 16 + nrow_off;
                    ldm_x4(bb[ng], sb + (128 + nr) * RSX + bcol);
                }
                #pragma unroll
                for (int mf = 0; mf < 4; mf++)
                    #pragma unroll
                    for (int ng = 0; ng < 2; ng++)
                        #pragma unroll
                        for (int sub = 0; sub < 2; sub++)
                            mma_f16(acc[mf][(hn * 2 + ng) * 2 + sub], af[mf], &bb[ng][sub * 2]);
            }
        }
        if (c + 1 < NC) {
            #pragma unroll
            for (int i = 0; i < 8; i++) {
                int brow = brow0 + 16 * i;
                *(uint4*)(so + (128 + brow) * RSX + bseg * 16) = dq8h(pw[i], ps[i], tab);
            }
        }
        CP_WAIT0();
        __syncthreads();
        if (c + 2 < NC) {
            const int k0 = (c + 2) * 64;
            #pragma unroll
            for (int i = 0; i < 8; i++) {
                int f = n0 + brow0 + 16 * i;
                pw[i] = *(const int4*)&we[(size_t)f * (I_ / 2) + (k0 >> 1) + bseg * 4];
                ps[i] = __uint_as_float((unsigned)se[(size_t)f * (I_ / 32) + (k0 >> 5) + (bseg >> 2)] << 23);
            }
        }
    }

    // epilogue: weighted scatter (comb * 64 compensates a/64)
    #pragma unroll
    for (int mf = 0; mf < 4; mf++) {
        const int rbase = wm * 64 + mf * 16 + (lid >> 2);
        #pragma unroll
        for (int half = 0; half < 2; half++) {
            int mrow = rbase + half * 8;
            int m = m0 + mrow;
            if (m < cnt) {
                int t = toks[mrow];
                float cw = g_comb[t * E_ + e] * 64.0f;
                float* orow = out + (size_t)t * D_ + n0;
                #pragma unroll
                for (int nf = 0; nf < 8; nf++) {
                    int col = wn * 64 + nf * 8 + (lid & 3) * 2;
                    atomicAdd(&orow[col],     cw * acc[mf][nf][half * 2 + 0]);
                    atomicAdd(&orow[col + 1], cw * acc[mf][nf][half * 2 + 1]);
                }
            }
        }
    }
}

// ---------------- launch ----------------
extern "C" void kernel_launch(void* const* d_in, const int* in_sizes, int n_in,
                              void* d_out, int out_size) {
    const float* hs   = (const float*)d_in[0];
    const float* tw   = (const float*)d_in[1];
    const int*   tids = (const int*)d_in[2];
    const int*   w13  = (const int*)d_in[3];
    const int*   w13s = (const int*)d_in[4];
    const int*   w2   = (const int*)d_in[5];
    const int*   w2s  = (const int*)d_in[6];
    float* out = (float*)d_out;

    cudaFuncSetAttribute(gemm1_kernel, cudaFuncAttributeMaxDynamicSharedMemorySize, DYN_SMEM);
    cudaFuncSetAttribute(gemm2_kernel, cudaFuncAttributeMaxDynamicSharedMemorySize, DYN_SMEM);

    prep_kernel<<<(T_ * D_ + 255) / 256, 256>>>(hs, tw, tids, out);
    route_compact_par<<<E_, T_>>>();

    dim3 g1(I_ / 64, T_ / 128, E_);    // 12 x 4 x 16
    gemm1_kernel<<<g1, 128, DYN_SMEM>>>(w13, w13s);

    dim3 g2(D_ / 128, T_ / 128, E_);   // 16 x 4 x 16
    gemm2_kernel<<<g2, 128, DYN_SMEM>>>(w2, w2s, out);
}